// round 9
// baseline (speedup 1.0000x reference)
#include <cuda_runtime.h>
#include <cuda_bf16.h>
#include <math.h>

// ---------------------------------------------------------------------------
// CfC recurrence v4: persistent weight-stationary kernel.
//   - per-CTA flag-array barriers (monotonic epochs, release/acquire)
//   - producer-granular staging: each staging thread polls only the flag of
//     the CTA that produced its half-row, then cp.async's it
//   - XOR-swizzled staging buffers (64-float rows), 4-buffer ring -> no
//     trailing __syncthreads needed between chunks
//   - 4x4 register tiles with fma.rn.f32x2 (unchanged from v3)
// B=64, T=1024, D=256, H=512, BU=512, Z=768. 128 CTAs x 256 threads.
// ---------------------------------------------------------------------------

#define Bc   64
#define Tc   1024
#define Dc   256
#define Hc   512
#define ZC   768
#define NCTA 128
#define NTHR 256
#define ZBUF (128 * 64)                 // one chunk buffer (floats)
#define WA_SEC 196
#define WB_SEC 2056
#define SMEM_FLOATS (16*WA_SEC + 4*WB_SEC + 4*ZBUF + 256 + 1024)
#define SMEM_BYTES  (SMEM_FLOATS * 4)

// -------------------- device-global state ----------------------------------
__device__ unsigned g_flagH[NCTA];      // epoch of last h written by CTA i
__device__ unsigned g_flagB[NCTA];      // epoch of last bb written by CTA i
__device__ __align__(256) float g_h [Hc * Bc];    // [col][b]
__device__ __align__(256) float g_bb[Hc * Bc];    // [col][b]
__device__ __align__(256) float g_xT[(size_t)Tc * Dc * Bc];   // [t][d][b]

// ------------------------------- helpers -----------------------------------
__device__ __forceinline__ void cp16(float* dst_smem, const float* src_gmem) {
    unsigned d = (unsigned)__cvta_generic_to_shared(dst_smem);
    asm volatile("cp.async.cg.shared.global [%0], [%1], 16;"
                 :: "r"(d), "l"(src_gmem) : "memory");
}
__device__ __forceinline__ void cp_commit() {
    asm volatile("cp.async.commit_group;" ::: "memory");
}
template <int N>
__device__ __forceinline__ void cp_wait() {
    asm volatile("cp.async.wait_group %0;" :: "n"(N) : "memory");
}

__device__ __forceinline__ void ffma2(unsigned long long& d,
                                      unsigned long long a,
                                      unsigned long long b) {
    asm("fma.rn.f32x2 %0, %1, %2, %0;" : "+l"(d) : "l"(a), "l"(b));
}
__device__ __forceinline__ void add2(unsigned long long& d,
                                     unsigned long long a,
                                     unsigned long long b) {
    asm("add.rn.f32x2 %0, %1, %2;" : "=l"(d) : "l"(a), "l"(b));
}
__device__ __forceinline__ unsigned long long dup2(float v) {
    unsigned long long r; unsigned u = __float_as_uint(v);
    asm("mov.b64 %0, {%1, %1};" : "=l"(r) : "r"(u));
    return r;
}
__device__ __forceinline__ float lo2(unsigned long long v) {
    return __uint_as_float((unsigned)v);
}
__device__ __forceinline__ float hi2(unsigned long long v) {
    return __uint_as_float((unsigned)(v >> 32));
}

__device__ __forceinline__ void mac16(unsigned long long* acc, float4 z,
                                      ulonglong2 w) {
    unsigned long long zz;
    zz = dup2(z.x); ffma2(acc[0], zz, w.x); ffma2(acc[1], zz, w.y);
    zz = dup2(z.y); ffma2(acc[2], zz, w.x); ffma2(acc[3], zz, w.y);
    zz = dup2(z.z); ffma2(acc[4], zz, w.x); ffma2(acc[5], zz, w.y);
    zz = dup2(z.w); ffma2(acc[6], zz, w.x); ffma2(acc[7], zz, w.y);
}

// ---- flag barrier primitives ----
__device__ __forceinline__ void flag_arrive(unsigned* flag, unsigned val) {
    __syncthreads();                     // all CTA threads done with stores
    if (threadIdx.x == 0) {
        __threadfence();                 // release stores to L2
        asm volatile("st.release.gpu.u32 [%0], %1;"
                     :: "l"(flag), "r"(val) : "memory");
    }
}
__device__ __forceinline__ void flag_poll(const unsigned* flag, unsigned tgt) {
    unsigned v;
    do {
        asm volatile("ld.acquire.gpu.u32 %0, [%1];"
                     : "=r"(v) : "l"(flag) : "memory");
    } while ((int)(v - tgt) < 0);
}

// Stage one 128-row chunk. Thread tid covers half-row: m = tid>>1, h = tid&1.
// If flags != nullptr, poll the producer CTA's flag first.
__device__ __forceinline__ void stage_chunk(float* buf,
                                            const float* __restrict__ src_base,
                                            const unsigned* flags,
                                            int cta_base, unsigned tgt) {
    int tid = threadIdx.x;
    int m = tid >> 1, h = tid & 1;
    if (flags) flag_poll(flags + cta_base + (m >> 2), tgt);
    const float* src = src_base + m * 64 + h * 32;
    float* dst = buf + m * 64 + h * 32;
    int f = (m >> 3) & 7;
#pragma unroll
    for (int i = 0; i < 8; i++)
        cp16(dst + ((i ^ f) << 2), src + i * 4);
    cp_commit();
}

// Phase A: one chunk, 8 k per thread, 4x4 tile.
__device__ __forceinline__ void gemmA_chunk(const float* __restrict__ buf,
                                            const float* __restrict__ wsec,
                                            int ks2, int rgA,
                                            unsigned long long* acc) {
    const float* zp = buf + (ks2 * 8) * 64 + (((rgA ^ (ks2 & 7)) & 15) << 2)
                      + ((rgA & 8) << 2);
    // note: rgA in 0..15; swizzle affects low 3 bits of quad index only:
    // stored quad = rgA ^ (ks2&7)  (bit3 of rgA preserved by xor<8)
    zp = buf + (ks2 * 8) * 64 + ((rgA ^ (ks2 & 7)) << 2);
#pragma unroll
    for (int i = 0; i < 8; i++) {
        float4 z = *(const float4*)(zp + i * 64);
        ulonglong2 w = *(const ulonglong2*)(wsec + i * 4);
        mac16(acc, z, w);
    }
}

// Phase B: one chunk, 32 k per thread, 4x4 tile (one matrix's 4 cols).
__device__ __forceinline__ void gemmB_chunk(const float* __restrict__ buf,
                                            const float* __restrict__ wsec,
                                            int km, int rgB,
                                            unsigned long long* acc) {
#pragma unroll
    for (int j = 0; j < 4; j++) {
        const float* zp = buf + (km * 32 + j * 8) * 64
                        + ((rgB ^ ((km * 4 + j) & 7)) << 2);
        const float* wp = wsec + j * 128;
#pragma unroll
        for (int i = 0; i < 8; i++) {
            float4 z = *(const float4*)(zp + i * 64);
            ulonglong2 w = *(const ulonglong2*)(wp + i * 16);
            mac16(acc, z, w);
        }
    }
}

// ------------------------- x transpose kernel ------------------------------
__global__ void __launch_bounds__(256) xpose_kernel(const float* __restrict__ x) {
    __shared__ float tile[32 * 65];
    int t = blockIdx.x;
    int tid = threadIdx.x;
    for (int dblk = 0; dblk < 8; dblk++) {
        int dl = tid & 31, bq = tid >> 5;
#pragma unroll
        for (int b8 = 0; b8 < 8; b8++) {
            int b = bq * 8 + b8;
            tile[dl * 65 + b] = x[((size_t)b * Tc + t) * Dc + dblk * 32 + dl];
        }
        __syncthreads();
        int b = tid & 63, dq = tid >> 6;
#pragma unroll
        for (int j = 0; j < 8; j++) {
            int d = dq * 8 + j;
            g_xT[((size_t)t * Dc + dblk * 32 + d) * Bc + b] = tile[d * 65 + b];
        }
        __syncthreads();
    }
}

// --------------------------------- kernel ----------------------------------
__global__ void __launch_bounds__(NTHR, 1)
cfc_persistent_kernel(const float* __restrict__ ts,
                      const float* __restrict__ h0,  const float* __restrict__ s0,
                      const float* __restrict__ Wbb, const float* __restrict__ bbb,
                      const float* __restrict__ Wff1,const float* __restrict__ bff1,
                      const float* __restrict__ Wff2,const float* __restrict__ bff2,
                      const float* __restrict__ Wta, const float* __restrict__ bta,
                      const float* __restrict__ Wtb, const float* __restrict__ btb,
                      float* __restrict__ out) {
    extern __shared__ float smem[];
    float* s_wA   = smem;                       // 16 x 196
    float* s_wB   = s_wA + 16 * WA_SEC;         // 4 x 2056
    float* s_z    = s_wB + 4 * WB_SEC;          // 4 x ZBUF
    float* s_redA = s_z + 4 * ZBUF;             // 256
    float* s_redB = s_redA + 256;               // 1024

    const int tid = threadIdx.x;
    const int bid = blockIdx.x;
    const int c0  = bid * 4;
    const int ks2 = tid & 15, rgA = tid >> 4;                 // phase A ids
    const int km = tid & 3, rgB = (tid >> 2) & 15, mB = tid >> 6;  // phase B
    const int ec = tid & 3, eb = tid >> 2;                    // epilogue ids
    const int cg = c0 + ec;
    const int eidx = ((eb >> 2) << 4) + ((eb & 3) << 2) + ec;

    // epoch bases (own flag; only this CTA writes it; equal across CTAs)
    const unsigned baseH = g_flagH[bid];
    const unsigned baseB = g_flagB[bid];

    // ---- one-time: weights -> sectioned SMEM (layouts unchanged from v3) ----
    for (int idx = tid; idx < ZC * 4; idx += NTHR) {
        int k = idx >> 2, cc = idx & 3;
        int sec = (k & 127) >> 3, ch = k >> 7, i = k & 7;
        s_wA[sec * WA_SEC + (ch * 8 + i) * 4 + cc] =
            __ldg(Wbb + (size_t)k * Hc + c0 + cc);
    }
    {
        const float* Wm[4] = {Wff1, Wff2, Wta, Wtb};
#pragma unroll
        for (int m = 0; m < 4; m++)
            for (int idx = tid; idx < Hc * 4; idx += NTHR) {
                int k = idx >> 2, cc = idx & 3;
                int sec = (k & 127) >> 5, ch = k >> 7, i = k & 31;
                s_wB[sec * WB_SEC + (ch * 32 + i) * 16 + m * 4 + cc] =
                    __ldg(Wm[m] + (size_t)k * Hc + c0 + cc);
            }
    }
    const float bbbc = __ldg(bbb  + cg);
    const float bf1c = __ldg(bff1 + cg);
    const float bf2c = __ldg(bff2 + cg);
    const float btac = __ldg(bta  + cg);
    const float btbc = __ldg(btb  + cg);

    float s_state = __ldg(s0 + (size_t)eb * Hc + cg);
    g_h[cg * Bc + eb] = __ldg(h0 + (size_t)eb * Hc + cg);

    float* zb0 = s_z;
    float* zb1 = s_z + ZBUF;
    float* zb2 = s_z + 2 * ZBUF;
    float* zb3 = s_z + 3 * ZBUF;

    flag_arrive(g_flagH + bid, baseH + 1);      // publish h0 (epoch base+1)

    // prefetch x(t=0) chunks A0 -> b0, A1 -> b1   (2 groups pending)
    stage_chunk(zb0, g_xT, nullptr, 0, 0);
    stage_chunk(zb1, g_xT + (size_t)128 * Bc, nullptr, 0, 0);

    for (int t = 0; t < Tc; t++) {
        const unsigned tgtH = baseH + (unsigned)t + 1;
        const unsigned tgtB = baseB + (unsigned)t + 1;

        // ============ Phase A: bb = silu(z @ Wbb + bbb), K=768 ============
        unsigned long long acc[8] = {0,0,0,0,0,0,0,0};
        // c=0
        stage_chunk(zb2, g_h,                 g_flagH, 0,  tgtH);   // A2
        cp_wait<2>(); __syncthreads();
        gemmA_chunk(zb0, s_wA + ks2 * WA_SEC + 0 * 32, ks2, rgA, acc);
        // c=1
        stage_chunk(zb3, g_h + 128 * Bc,      g_flagH, 32, tgtH);   // A3
        cp_wait<2>(); __syncthreads();
        gemmA_chunk(zb1, s_wA + ks2 * WA_SEC + 1 * 32, ks2, rgA, acc);
        // c=2
        stage_chunk(zb0, g_h + 256 * Bc,      g_flagH, 64, tgtH);   // A4
        cp_wait<2>(); __syncthreads();
        gemmA_chunk(zb2, s_wA + ks2 * WA_SEC + 2 * 32, ks2, rgA, acc);
        // c=3
        stage_chunk(zb1, g_h + 384 * Bc,      g_flagH, 96, tgtH);   // A5
        cp_wait<2>(); __syncthreads();
        gemmA_chunk(zb3, s_wA + ks2 * WA_SEC + 3 * 32, ks2, rgA, acc);
        // c=4
        cp_wait<1>(); __syncthreads();
        gemmA_chunk(zb0, s_wA + ks2 * WA_SEC + 4 * 32, ks2, rgA, acc);
        // c=5
        cp_wait<0>(); __syncthreads();
        gemmA_chunk(zb1, s_wA + ks2 * WA_SEC + 5 * 32, ks2, rgA, acc);

        // reduce 16-way ksplit (lane bits 0..3)
#pragma unroll
        for (int d = 1; d <= 8; d <<= 1)
#pragma unroll
            for (int q = 0; q < 8; q++) {
                unsigned long long o = __shfl_xor_sync(0xffffffffu, acc[q], d);
                add2(acc[q], acc[q], o);
            }
        if ((tid & 15) == 0) {
            float* dst = s_redA + rgA * 16;
#pragma unroll
            for (int r = 0; r < 4; r++) {
                float4 v = make_float4(lo2(acc[2*r]), hi2(acc[2*r]),
                                       lo2(acc[2*r+1]), hi2(acc[2*r+1]));
                *(float4*)(dst + r * 4) = v;
            }
        }
        __syncthreads();
        {
            float av  = s_redA[eidx] + bbbc;
            float bbv = av / (1.0f + expf(-av));       // silu
            g_bb[cg * Bc + eb] = bbv;
        }
        flag_arrive(g_flagB + bid, tgtB);              // own bb published

        // per-thread ts math (overlaps with staging polls below)
        float tstv = __ldg(ts + (size_t)eb * Tc + t);
        float tn   = 1.0f / tstv;
        float wts  = (tn > 0.0f) ? expf(tn * (1.0f - 2.0f * logf(tn))) : 0.0f;

        // ====== Phase B: 4 GEMMs over bb (K=512); gate & update ======
        unsigned long long fac[8] = {0,0,0,0,0,0,0,0};
        const int t1 = (t + 1 < Tc) ? t + 1 : t;       // clamp prefetch
        stage_chunk(zb0, g_bb,                g_flagB, 0,  tgtB);   // B0
        stage_chunk(zb1, g_bb + 128 * Bc,     g_flagB, 32, tgtB);   // B1
        // c=0
        stage_chunk(zb2, g_bb + 256 * Bc,     g_flagB, 64, tgtB);   // B2
        cp_wait<2>(); __syncthreads();
        gemmB_chunk(zb0, s_wB + km * WB_SEC + 0 * 512 + mB * 4, km, rgB, fac);
        // c=1
        stage_chunk(zb3, g_bb + 384 * Bc,     g_flagB, 96, tgtB);   // B3
        cp_wait<2>(); __syncthreads();
        gemmB_chunk(zb1, s_wB + km * WB_SEC + 1 * 512 + mB * 4, km, rgB, fac);
        // c=2  (prefetch next x chunk 0 into b0)
        stage_chunk(zb0, g_xT + ((size_t)t1 * Dc) * Bc, nullptr, 0, 0);
        cp_wait<2>(); __syncthreads();
        gemmB_chunk(zb2, s_wB + km * WB_SEC + 2 * 512 + mB * 4, km, rgB, fac);
        // c=3  (prefetch next x chunk 1 into b1)
        stage_chunk(zb1, g_xT + ((size_t)t1 * Dc + 128) * Bc, nullptr, 0, 0);
        cp_wait<2>(); __syncthreads();
        gemmB_chunk(zb3, s_wB + km * WB_SEC + 3 * 512 + mB * 4, km, rgB, fac);

        // reduce 4-way ksplit (lane bits 0..1)
#pragma unroll
        for (int d = 1; d <= 2; d <<= 1)
#pragma unroll
            for (int q = 0; q < 8; q++) {
                unsigned long long o = __shfl_xor_sync(0xffffffffu, fac[q], d);
                add2(fac[q], fac[q], o);
            }
        if ((tid & 3) == 0) {
            float* dst = s_redB + mB * 256 + rgB * 16;
#pragma unroll
            for (int r = 0; r < 4; r++) {
                float4 v = make_float4(lo2(fac[2*r]), hi2(fac[2*r]),
                                       lo2(fac[2*r+1]), hi2(fac[2*r+1]));
                *(float4*)(dst + r * 4) = v;
            }
        }
        __syncthreads();
        {
            float p0 = s_redB[0 * 256 + eidx];
            float p1 = s_redB[1 * 256 + eidx];
            float p2 = s_redB[2 * 256 + eidx];
            float p3 = s_redB[3 * 256 + eidx];
            float ff1 = tanhf(p0 + bf1c);
            float ff2 = tanhf(p1 + bf2c);
            s_state += (p2 + btac) * wts + (p3 + btbc);
            float ti = 1.0f / (1.0f + expf(-s_state));
            float hn = ff1 + ti * (ff2 - ff1);
            g_h[cg * Bc + eb] = hn;
            out[((size_t)eb * Tc + t) * Hc + cg] = hn;
        }
        flag_arrive(g_flagH + bid, tgtH + 1);          // h(t+1) published
    }
    cp_wait<0>();
}

// --------------------------------- launch ----------------------------------
extern "C" void kernel_launch(void* const* d_in, const int* in_sizes, int n_in,
                              void* d_out, int out_size) {
    (void)in_sizes; (void)n_in; (void)out_size;
    cudaFuncSetAttribute(cfc_persistent_kernel,
                         cudaFuncAttributeMaxDynamicSharedMemorySize, SMEM_BYTES);
    xpose_kernel<<<Tc, 256>>>((const float*)d_in[0]);
    cfc_persistent_kernel<<<NCTA, NTHR, SMEM_BYTES>>>(
        (const float*)d_in[1],
        (const float*)d_in[2],  (const float*)d_in[3],
        (const float*)d_in[4],  (const float*)d_in[5],
        (const float*)d_in[6],  (const float*)d_in[7],
        (const float*)d_in[8],  (const float*)d_in[9],
        (const float*)d_in[10], (const float*)d_in[11],
        (const float*)d_in[12], (const float*)d_in[13],
        (float*)d_out);
}

// round 10
// speedup vs baseline: 1.0790x; 1.0790x over previous
#include <cuda_runtime.h>
#include <cuda_bf16.h>
#include <math.h>

// ---------------------------------------------------------------------------
// CfC recurrence v5: persistent weight-stationary kernel.
//   - monolithic split global barrier (thread-0 atomicAdd + spin) [R8 proven]
//   - 5-buffer XOR-swizzled staging ring, all chunks of a phase issued
//     back-to-back right after the barrier (deep cp.async pipeline)
//   - 4x4 register tiles with fma.rn.f32x2 [R8 proven]
// B=64, T=1024, D=256, H=512, BU=512, Z=768. 128 CTAs x 256 threads.
// ---------------------------------------------------------------------------

#define Bc   64
#define Tc   1024
#define Dc   256
#define Hc   512
#define ZC   768
#define NCTA 128
#define NTHR 256
#define ZBUF (128 * 64)                 // one chunk buffer (floats)
#define WA_SEC 196
#define WB_SEC 2056
#define SMEM_FLOATS (16*WA_SEC + 4*WB_SEC + 5*ZBUF + 256 + 1024)
#define SMEM_BYTES  (SMEM_FLOATS * 4)

// -------------------- device-global state ----------------------------------
__device__ unsigned g_count = 0;
__device__ unsigned g_sense = 0;
__device__ __align__(256) float g_h [Hc * Bc];    // [col][b]
__device__ __align__(256) float g_bb[Hc * Bc];    // [col][b]
__device__ __align__(256) float g_xT[(size_t)Tc * Dc * Bc];   // [t][d][b]

// ------------------------------- helpers -----------------------------------
__device__ __forceinline__ void cp16(float* dst_smem, const float* src_gmem) {
    unsigned d = (unsigned)__cvta_generic_to_shared(dst_smem);
    asm volatile("cp.async.cg.shared.global [%0], [%1], 16;"
                 :: "r"(d), "l"(src_gmem) : "memory");
}
__device__ __forceinline__ void cp_commit() {
    asm volatile("cp.async.commit_group;" ::: "memory");
}
template <int N>
__device__ __forceinline__ void cp_wait() {
    asm volatile("cp.async.wait_group %0;" :: "n"(N) : "memory");
}

__device__ __forceinline__ void ffma2(unsigned long long& d,
                                      unsigned long long a,
                                      unsigned long long b) {
    asm("fma.rn.f32x2 %0, %1, %2, %0;" : "+l"(d) : "l"(a), "l"(b));
}
__device__ __forceinline__ void add2(unsigned long long& d,
                                     unsigned long long a,
                                     unsigned long long b) {
    asm("add.rn.f32x2 %0, %1, %2;" : "=l"(d) : "l"(a), "l"(b));
}
__device__ __forceinline__ unsigned long long dup2(float v) {
    unsigned long long r; unsigned u = __float_as_uint(v);
    asm("mov.b64 %0, {%1, %1};" : "=l"(r) : "r"(u));
    return r;
}
__device__ __forceinline__ float lo2(unsigned long long v) {
    return __uint_as_float((unsigned)v);
}
__device__ __forceinline__ float hi2(unsigned long long v) {
    return __uint_as_float((unsigned)(v >> 32));
}

__device__ __forceinline__ void mac16(unsigned long long* acc, float4 z,
                                      ulonglong2 w) {
    unsigned long long zz;
    zz = dup2(z.x); ffma2(acc[0], zz, w.x); ffma2(acc[1], zz, w.y);
    zz = dup2(z.y); ffma2(acc[2], zz, w.x); ffma2(acc[3], zz, w.y);
    zz = dup2(z.z); ffma2(acc[4], zz, w.x); ffma2(acc[5], zz, w.y);
    zz = dup2(z.w); ffma2(acc[6], zz, w.x); ffma2(acc[7], zz, w.y);
}

// ---- monolithic split global barrier (R8 proven) ----
__device__ __forceinline__ void gbar_arrive(unsigned sense0, unsigned& ep) {
    __syncthreads();
    ep++;
    if (threadIdx.x == 0) {
        __threadfence();
        if (atomicAdd(&g_count, 1u) == (unsigned)(NCTA - 1)) {
            atomicExch(&g_count, 0u);
            asm volatile("st.release.gpu.u32 [%0], %1;"
                         :: "l"(&g_sense), "r"(sense0 + ep) : "memory");
        }
    }
}
__device__ __forceinline__ void gbar_wait(unsigned sense0, unsigned ep) {
    if (threadIdx.x == 0) {
        unsigned v, target = sense0 + ep;
        do {
            asm volatile("ld.acquire.gpu.u32 %0, [%1];"
                         : "=r"(v) : "l"(&g_sense) : "memory");
        } while (v != target);
    }
    __syncthreads();
}

// Stage one 128-row chunk (rows of 64 floats), XOR-swizzled (v4-validated).
__device__ __forceinline__ void stage_chunk(float* buf,
                                            const float* __restrict__ src_base) {
    int tid = threadIdx.x;
    int m = tid >> 1, h = tid & 1;
    const float* src = src_base + m * 64 + h * 32;
    float* dst = buf + m * 64 + h * 32;
    int f = (m >> 3) & 7;
#pragma unroll
    for (int i = 0; i < 8; i++)
        cp16(dst + ((i ^ f) << 2), src + i * 4);
    cp_commit();
}

// Phase A: one chunk, 8 k per thread, 4x4 tile (v4-validated indexing).
__device__ __forceinline__ void gemmA_chunk(const float* __restrict__ buf,
                                            const float* __restrict__ wsec,
                                            int ks2, int rgA,
                                            unsigned long long* acc) {
    const float* zp = buf + (ks2 * 8) * 64 + ((rgA ^ (ks2 & 7)) << 2);
#pragma unroll
    for (int i = 0; i < 8; i++) {
        float4 z = *(const float4*)(zp + i * 64);
        ulonglong2 w = *(const ulonglong2*)(wsec + i * 4);
        mac16(acc, z, w);
    }
}

// Phase B: one chunk, 32 k per thread, 4x4 tile (v4-validated indexing).
__device__ __forceinline__ void gemmB_chunk(const float* __restrict__ buf,
                                            const float* __restrict__ wsec,
                                            int km, int rgB,
                                            unsigned long long* acc) {
#pragma unroll
    for (int j = 0; j < 4; j++) {
        const float* zp = buf + (km * 32 + j * 8) * 64
                        + ((rgB ^ ((km * 4 + j) & 7)) << 2);
        const float* wp = wsec + j * 128;
#pragma unroll
        for (int i = 0; i < 8; i++) {
            float4 z = *(const float4*)(zp + i * 64);
            ulonglong2 w = *(const ulonglong2*)(wp + i * 16);
            mac16(acc, z, w);
        }
    }
}

// ------------------------- x transpose kernel ------------------------------
__global__ void __launch_bounds__(256) xpose_kernel(const float* __restrict__ x) {
    __shared__ float tile[32 * 65];
    int t = blockIdx.x;
    int tid = threadIdx.x;
    for (int dblk = 0; dblk < 8; dblk++) {
        int dl = tid & 31, bq = tid >> 5;
#pragma unroll
        for (int b8 = 0; b8 < 8; b8++) {
            int b = bq * 8 + b8;
            tile[dl * 65 + b] = x[((size_t)b * Tc + t) * Dc + dblk * 32 + dl];
        }
        __syncthreads();
        int b = tid & 63, dq = tid >> 6;
#pragma unroll
        for (int j = 0; j < 8; j++) {
            int d = dq * 8 + j;
            g_xT[((size_t)t * Dc + dblk * 32 + d) * Bc + b] = tile[d * 65 + b];
        }
        __syncthreads();
    }
}

// --------------------------------- kernel ----------------------------------
__global__ void __launch_bounds__(NTHR, 1)
cfc_persistent_kernel(const float* __restrict__ ts,
                      const float* __restrict__ h0,  const float* __restrict__ s0,
                      const float* __restrict__ Wbb, const float* __restrict__ bbb,
                      const float* __restrict__ Wff1,const float* __restrict__ bff1,
                      const float* __restrict__ Wff2,const float* __restrict__ bff2,
                      const float* __restrict__ Wta, const float* __restrict__ bta,
                      const float* __restrict__ Wtb, const float* __restrict__ btb,
                      float* __restrict__ out) {
    extern __shared__ float smem[];
    float* s_wA   = smem;                       // 16 x 196
    float* s_wB   = s_wA + 16 * WA_SEC;         // 4 x 2056
    float* s_z    = s_wB + 4 * WB_SEC;          // 5 x ZBUF
    float* s_redA = s_z + 5 * ZBUF;             // 256
    float* s_redB = s_redA + 256;               // 1024

    const int tid = threadIdx.x;
    const int c0  = blockIdx.x * 4;
    const int ks2 = tid & 15, rgA = tid >> 4;                      // phase A
    const int km = tid & 3, rgB = (tid >> 2) & 15, mB = tid >> 6;  // phase B
    const int ec = tid & 3, eb = tid >> 2;                         // epilogue
    const int cg = c0 + ec;
    const int eidx = ((eb >> 2) << 4) + ((eb & 3) << 2) + ec;

    // ---- one-time: weights -> sectioned SMEM (R8-exact layouts) ----
    for (int idx = tid; idx < ZC * 4; idx += NTHR) {
        int k = idx >> 2, cc = idx & 3;
        int sec = (k & 127) >> 3, ch = k >> 7, i = k & 7;
        s_wA[sec * WA_SEC + (ch * 8 + i) * 4 + cc] =
            __ldg(Wbb + (size_t)k * Hc + c0 + cc);
    }
    {
        const float* Wm[4] = {Wff1, Wff2, Wta, Wtb};
#pragma unroll
        for (int m = 0; m < 4; m++)
            for (int idx = tid; idx < Hc * 4; idx += NTHR) {
                int k = idx >> 2, cc = idx & 3;
                int sec = (k & 127) >> 5, ch = k >> 7, i = k & 31;
                s_wB[sec * WB_SEC + (ch * 32 + i) * 16 + m * 4 + cc] =
                    __ldg(Wm[m] + (size_t)k * Hc + c0 + cc);
            }
    }
    const float bbbc = __ldg(bbb  + cg);
    const float bf1c = __ldg(bff1 + cg);
    const float bf2c = __ldg(bff2 + cg);
    const float btac = __ldg(bta  + cg);
    const float btbc = __ldg(btb  + cg);

    float s_state = __ldg(s0 + (size_t)eb * Hc + cg);
    g_h[cg * Bc + eb] = __ldg(h0 + (size_t)eb * Hc + cg);

    float* zb[5] = {s_z, s_z + ZBUF, s_z + 2 * ZBUF, s_z + 3 * ZBUF,
                    s_z + 4 * ZBUF};

    unsigned sense0 = 0, ep = 0;
    if (tid == 0) {
        asm volatile("ld.acquire.gpu.u32 %0, [%1];"
                     : "=r"(sense0) : "l"(&g_sense) : "memory");
    }

    gbar_arrive(sense0, ep);                     // publish h0
    // prefetch x(0): X0 -> b4, X1 -> b0   (2 outstanding groups at loop entry)
    stage_chunk(zb[4], g_xT);
    stage_chunk(zb[0], g_xT + (size_t)128 * Bc);
    gbar_wait(sense0, ep);

    for (int t = 0; t < Tc; t++) {
        // ============ Phase A: bb = silu(z @ Wbb + bbb), K=768 ============
        unsigned long long acc[8] = {0,0,0,0,0,0,0,0};
        // issue all h staging back-to-back (deep pipeline)
        stage_chunk(zb[1], g_h);                 // H0
        stage_chunk(zb[2], g_h + 128 * Bc);      // H1
        stage_chunk(zb[3], g_h + 256 * Bc);      // H2
        // outstanding: X0,X1,H0,H1,H2 (5)
        cp_wait<4>(); __syncthreads();
        gemmA_chunk(zb[4], s_wA + ks2 * WA_SEC + 0 * 32, ks2, rgA, acc); // X0
        __syncthreads();
        stage_chunk(zb[4], g_h + 384 * Bc);      // H3 reuses b4
        cp_wait<4>(); __syncthreads();
        gemmA_chunk(zb[0], s_wA + ks2 * WA_SEC + 1 * 32, ks2, rgA, acc); // X1
        cp_wait<3>(); __syncthreads();
        gemmA_chunk(zb[1], s_wA + ks2 * WA_SEC + 2 * 32, ks2, rgA, acc); // H0
        cp_wait<2>(); __syncthreads();
        gemmA_chunk(zb[2], s_wA + ks2 * WA_SEC + 3 * 32, ks2, rgA, acc); // H1
        cp_wait<1>(); __syncthreads();
        gemmA_chunk(zb[3], s_wA + ks2 * WA_SEC + 4 * 32, ks2, rgA, acc); // H2
        cp_wait<0>(); __syncthreads();
        gemmA_chunk(zb[4], s_wA + ks2 * WA_SEC + 5 * 32, ks2, rgA, acc); // H3

        // reduce 16-way ksplit (lane bits 0..3)
#pragma unroll
        for (int d = 1; d <= 8; d <<= 1)
#pragma unroll
            for (int q = 0; q < 8; q++) {
                unsigned long long o = __shfl_xor_sync(0xffffffffu, acc[q], d);
                add2(acc[q], acc[q], o);
            }
        if ((tid & 15) == 0) {
            float* dst = s_redA + rgA * 16;
#pragma unroll
            for (int r = 0; r < 4; r++) {
                float4 v = make_float4(lo2(acc[2*r]), hi2(acc[2*r]),
                                       lo2(acc[2*r+1]), hi2(acc[2*r+1]));
                *(float4*)(dst + r * 4) = v;
            }
        }
        __syncthreads();
        {
            float av  = s_redA[eidx] + bbbc;
            float bbv = av / (1.0f + expf(-av));       // silu
            g_bb[cg * Bc + eb] = bbv;
        }
        gbar_arrive(sense0, ep);                        // bb barrier
        float tstv = __ldg(ts + (size_t)eb * Tc + t);   // hidden under spin
        float tn   = 1.0f / tstv;
        float wts  = (tn > 0.0f) ? expf(tn * (1.0f - 2.0f * logf(tn))) : 0.0f;
        gbar_wait(sense0, ep);

        // ====== Phase B: 4 GEMMs over bb (K=512); gate & update ======
        unsigned long long fac[8] = {0,0,0,0,0,0,0,0};
        const int t1 = (t + 1 < Tc) ? t + 1 : t;
        // issue all bb staging + x(t+1) chunk0 back-to-back
        stage_chunk(zb[0], g_bb);                // B0
        stage_chunk(zb[1], g_bb + 128 * Bc);     // B1
        stage_chunk(zb[2], g_bb + 256 * Bc);     // B2
        stage_chunk(zb[3], g_bb + 384 * Bc);     // B3
        stage_chunk(zb[4], g_xT + ((size_t)t1 * Dc) * Bc);          // X0(t+1)
        cp_wait<4>(); __syncthreads();
        gemmB_chunk(zb[0], s_wB + km * WB_SEC + 0 * 512 + mB * 4, km, rgB, fac);
        __syncthreads();
        stage_chunk(zb[0], g_xT + ((size_t)t1 * Dc + 128) * Bc);    // X1(t+1)
        cp_wait<4>(); __syncthreads();
        gemmB_chunk(zb[1], s_wB + km * WB_SEC + 1 * 512 + mB * 4, km, rgB, fac);
        cp_wait<3>(); __syncthreads();
        gemmB_chunk(zb[2], s_wB + km * WB_SEC + 2 * 512 + mB * 4, km, rgB, fac);
        cp_wait<2>(); __syncthreads();
        gemmB_chunk(zb[3], s_wB + km * WB_SEC + 3 * 512 + mB * 4, km, rgB, fac);
        // outstanding after phase B: X0(t+1), X1(t+1)  — matches loop entry

        // reduce 4-way ksplit (lane bits 0..1)
#pragma unroll
        for (int d = 1; d <= 2; d <<= 1)
#pragma unroll
            for (int q = 0; q < 8; q++) {
                unsigned long long o = __shfl_xor_sync(0xffffffffu, fac[q], d);
                add2(fac[q], fac[q], o);
            }
        if ((tid & 3) == 0) {
            float* dst = s_redB + mB * 256 + rgB * 16;
#pragma unroll
            for (int r = 0; r < 4; r++) {
                float4 v = make_float4(lo2(fac[2*r]), hi2(fac[2*r]),
                                       lo2(fac[2*r+1]), hi2(fac[2*r+1]));
                *(float4*)(dst + r * 4) = v;
            }
        }
        __syncthreads();
        {
            float p0 = s_redB[0 * 256 + eidx];
            float p1 = s_redB[1 * 256 + eidx];
            float p2 = s_redB[2 * 256 + eidx];
            float p3 = s_redB[3 * 256 + eidx];
            float ff1 = tanhf(p0 + bf1c);
            float ff2 = tanhf(p1 + bf2c);
            s_state += (p2 + btac) * wts + (p3 + btbc);
            float ti = 1.0f / (1.0f + expf(-s_state));
            float hn = ff1 + ti * (ff2 - ff1);
            g_h[cg * Bc + eb] = hn;
            out[((size_t)eb * Tc + t) * Hc + cg] = hn;
        }
        gbar_arrive(sense0, ep);                        // h barrier
        gbar_wait(sense0, ep);
    }
    cp_wait<0>();
}

// --------------------------------- launch ----------------------------------
extern "C" void kernel_launch(void* const* d_in, const int* in_sizes, int n_in,
                              void* d_out, int out_size) {
    (void)in_sizes; (void)n_in; (void)out_size;
    cudaFuncSetAttribute(cfc_persistent_kernel,
                         cudaFuncAttributeMaxDynamicSharedMemorySize, SMEM_BYTES);
    xpose_kernel<<<Tc, 256>>>((const float*)d_in[0]);
    cfc_persistent_kernel<<<NCTA, NTHR, SMEM_BYTES>>>(
        (const float*)d_in[1],
        (const float*)d_in[2],  (const float*)d_in[3],
        (const float*)d_in[4],  (const float*)d_in[5],
        (const float*)d_in[6],  (const float*)d_in[7],
        (const float*)d_in[8],  (const float*)d_in[9],
        (const float*)d_in[10], (const float*)d_in[11],
        (const float*)d_in[12], (const float*)d_in[13],
        (float*)d_out);
}

// round 11
// speedup vs baseline: 2.0838x; 1.9312x over previous
#include <cuda_runtime.h>
#include <cuda_bf16.h>
#include <math.h>

// ---------------------------------------------------------------------------
// CfC recurrence v6 = R8 (proven 16.58ms) + two surgical fixes:
//   1) phase-B thread remap (rgB in low lane bits) -> conflict-free z LDS
//   2) phase-A x-chunks computed BEFORE the h-barrier wait (barrier shadow)
// Staging function, ZROW=96 padded layout, weight layouts, barrier: R8-exact.
// B=64, T=1024, D=256, H=512, BU=512, Z=768. 128 CTAs x 256 threads.
// ---------------------------------------------------------------------------

#define Bc   64
#define Tc   1024
#define Dc   256
#define Hc   512
#define ZC   768
#define NCTA 128
#define NTHR 256
#define ZROW 96                         // staged z row stride (floats)
#define ZBUF (128 * ZROW)               // one chunk buffer: 128 rows
#define WA_SEC 196
#define WB_SEC 2056
#define REDB_SEC 320                    // [16 rgB][20] padded
#define SMEM_FLOATS (16*WA_SEC + 4*WB_SEC + 3*ZBUF + 256 + 8*REDB_SEC)
#define SMEM_BYTES  (SMEM_FLOATS * 4)

// -------------------- device-global state ----------------------------------
__device__ unsigned g_count = 0;
__device__ unsigned g_sense = 0;
__device__ __align__(256) float g_h [Hc * Bc];    // [col][b]
__device__ __align__(256) float g_bb[Hc * Bc];    // [col][b]
__device__ __align__(256) float g_xT[(size_t)Tc * Dc * Bc];   // [t][d][b]

// ------------------------------- helpers -----------------------------------
__device__ __forceinline__ void cp16(float* dst_smem, const float* src_gmem) {
    unsigned d = (unsigned)__cvta_generic_to_shared(dst_smem);
    asm volatile("cp.async.cg.shared.global [%0], [%1], 16;"
                 :: "r"(d), "l"(src_gmem) : "memory");
}
__device__ __forceinline__ void cp_commit() {
    asm volatile("cp.async.commit_group;" ::: "memory");
}
template <int N>
__device__ __forceinline__ void cp_wait() {
    asm volatile("cp.async.wait_group %0;" :: "n"(N) : "memory");
}

__device__ __forceinline__ void ffma2(unsigned long long& d,
                                      unsigned long long a,
                                      unsigned long long b) {
    asm("fma.rn.f32x2 %0, %1, %2, %0;" : "+l"(d) : "l"(a), "l"(b));
}
__device__ __forceinline__ void add2(unsigned long long& d,
                                     unsigned long long a,
                                     unsigned long long b) {
    asm("add.rn.f32x2 %0, %1, %2;" : "=l"(d) : "l"(a), "l"(b));
}
__device__ __forceinline__ unsigned long long dup2(float v) {
    unsigned long long r; unsigned u = __float_as_uint(v);
    asm("mov.b64 %0, {%1, %1};" : "=l"(r) : "r"(u));
    return r;
}
__device__ __forceinline__ float lo2(unsigned long long v) {
    return __uint_as_float((unsigned)v);
}
__device__ __forceinline__ float hi2(unsigned long long v) {
    return __uint_as_float((unsigned)(v >> 32));
}

__device__ __forceinline__ void mac16(unsigned long long* acc, float4 z,
                                      ulonglong2 w) {
    unsigned long long zz;
    zz = dup2(z.x); ffma2(acc[0], zz, w.x); ffma2(acc[1], zz, w.y);
    zz = dup2(z.y); ffma2(acc[2], zz, w.x); ffma2(acc[3], zz, w.y);
    zz = dup2(z.z); ffma2(acc[4], zz, w.x); ffma2(acc[5], zz, w.y);
    zz = dup2(z.w); ffma2(acc[6], zz, w.x); ffma2(acc[7], zz, w.y);
}

// ---- monolithic split global barrier (R8-exact) ----
__device__ __forceinline__ void gbar_arrive(unsigned sense0, unsigned& ep) {
    __syncthreads();
    ep++;
    if (threadIdx.x == 0) {
        __threadfence();
        if (atomicAdd(&g_count, 1u) == (unsigned)(NCTA - 1)) {
            atomicExch(&g_count, 0u);
            asm volatile("st.release.gpu.u32 [%0], %1;"
                         :: "l"(&g_sense), "r"(sense0 + ep) : "memory");
        }
    }
}
__device__ __forceinline__ void gbar_wait(unsigned sense0, unsigned ep) {
    if (threadIdx.x == 0) {
        unsigned v, target = sense0 + ep;
        do {
            asm volatile("ld.acquire.gpu.u32 %0, [%1];"
                         : "=r"(v) : "l"(&g_sense) : "memory");
        } while (v != target);
    }
    __syncthreads();
}

// Stage one 128-row k-chunk (R8-exact: fully coalesced, row-group skew).
__device__ __forceinline__ void stage_chunk(float* buf,
                                            const float* __restrict__ src) {
    int tid = threadIdx.x;
#pragma unroll
    for (int i = 0; i < 8; i++) {
        int lin = tid + i * NTHR;           // 0..2047
        int l   = lin >> 4;                 // row 0..127
        int b4  = (lin & 15) << 2;          // float4 col
        cp16(buf + l * ZROW + (((l >> 3) & 7) << 2) + b4,
             src + l * Bc + b4);
    }
    cp_commit();
}

// Phase A: one chunk (8 k per thread), 4x4 tile (R8-exact, conflict-free).
__device__ __forceinline__ void gemmA_chunk(const float* __restrict__ buf,
                                            const float* __restrict__ wsec,
                                            int ks2, int rgA,
                                            unsigned long long* acc) {
    const float* zp = buf + (ks2 * 8) * ZROW + ((ks2 & 7) << 2) + (rgA << 2);
#pragma unroll
    for (int i = 0; i < 8; i++) {
        float4 z = *(const float4*)(zp + i * ZROW);
        ulonglong2 w = *(const ulonglong2*)(wsec + i * 4);
        mac16(acc, z, w);
    }
}

// Phase B: one chunk (32 k per thread), 4x4 tile. Same addressing as R8 but
// with rgB sourced from LOW lane bits -> conflict-free z (8 distinct quads
// per quarter-warp phase); w stays broadcast.
__device__ __forceinline__ void gemmB_chunk(const float* __restrict__ buf,
                                            const float* __restrict__ wsec,
                                            int km, int rgB,
                                            unsigned long long* acc) {
    const float* zb = buf + (km * 32) * ZROW + (rgB << 2);
#pragma unroll
    for (int j = 0; j < 4; j++) {
        const float* zp = zb + (j * 8) * ZROW + ((((km << 2) + j) & 7) << 2);
        const float* wp = wsec + j * 128;
#pragma unroll
        for (int i = 0; i < 8; i++) {
            float4 z = *(const float4*)(zp + i * ZROW);
            ulonglong2 w = *(const ulonglong2*)(wp + i * 16);
            mac16(acc, z, w);
        }
    }
}

// ------------------------- x transpose kernel ------------------------------
__global__ void __launch_bounds__(256) xpose_kernel(const float* __restrict__ x) {
    __shared__ float tile[32 * 65];
    int t = blockIdx.x;
    int tid = threadIdx.x;
    for (int dblk = 0; dblk < 8; dblk++) {
        int dl = tid & 31, bq = tid >> 5;
#pragma unroll
        for (int b8 = 0; b8 < 8; b8++) {
            int b = bq * 8 + b8;
            tile[dl * 65 + b] = x[((size_t)b * Tc + t) * Dc + dblk * 32 + dl];
        }
        __syncthreads();
        int b = tid & 63, dq = tid >> 6;
#pragma unroll
        for (int j = 0; j < 8; j++) {
            int d = dq * 8 + j;
            g_xT[((size_t)t * Dc + dblk * 32 + d) * Bc + b] = tile[d * 65 + b];
        }
        __syncthreads();
    }
}

// --------------------------------- kernel ----------------------------------
__global__ void __launch_bounds__(NTHR, 1)
cfc_persistent_kernel(const float* __restrict__ ts,
                      const float* __restrict__ h0,  const float* __restrict__ s0,
                      const float* __restrict__ Wbb, const float* __restrict__ bbb,
                      const float* __restrict__ Wff1,const float* __restrict__ bff1,
                      const float* __restrict__ Wff2,const float* __restrict__ bff2,
                      const float* __restrict__ Wta, const float* __restrict__ bta,
                      const float* __restrict__ Wtb, const float* __restrict__ btb,
                      float* __restrict__ out) {
    extern __shared__ float smem[];
    float* s_wA   = smem;                       // 16 x 196
    float* s_wB   = s_wA + 16 * WA_SEC;         // 4 x 2056
    float* s_z    = s_wB + 4 * WB_SEC;          // 3 x ZBUF
    float* s_redA = s_z + 3 * ZBUF;             // 256
    float* s_redB = s_redA + 256;               // 8 x 320

    const int tid = threadIdx.x;
    const int c0  = blockIdx.x * 4;
    const int lane = tid & 31, warp = tid >> 5;
    // phase A ids (R8-exact)
    const int ks2 = tid & 15, rgA = tid >> 4;
    // phase B ids (REMAPPED: rgB low bits)
    const int rgB = tid & 15, km = (tid >> 4) & 3, mB = tid >> 6;
    // epilogue ids
    const int ec = tid & 3, eb = tid >> 2;
    const int cg = c0 + ec;
    const int eidxA = ((eb >> 2) << 4) + ((eb & 3) << 2) + ec;
    const int eoffB = (eb >> 2) * 20 + (eb & 3) * 4 + ec;

    // ---- one-time: weights -> sectioned SMEM (R8-exact layouts) ----
    for (int idx = tid; idx < ZC * 4; idx += NTHR) {
        int k = idx >> 2, cc = idx & 3;
        int sec = (k & 127) >> 3, ch = k >> 7, i = k & 7;
        s_wA[sec * WA_SEC + (ch * 8 + i) * 4 + cc] =
            __ldg(Wbb + (size_t)k * Hc + c0 + cc);
    }
    {
        const float* Wm[4] = {Wff1, Wff2, Wta, Wtb};
#pragma unroll
        for (int m = 0; m < 4; m++)
            for (int idx = tid; idx < Hc * 4; idx += NTHR) {
                int k = idx >> 2, cc = idx & 3;
                int sec = (k & 127) >> 5, ch = k >> 7, i = k & 31;
                s_wB[sec * WB_SEC + (ch * 32 + i) * 16 + m * 4 + cc] =
                    __ldg(Wm[m] + (size_t)k * Hc + c0 + cc);
            }
    }
    const float bbbc = __ldg(bbb  + cg);
    const float bf1c = __ldg(bff1 + cg);
    const float bf2c = __ldg(bff2 + cg);
    const float btac = __ldg(bta  + cg);
    const float btbc = __ldg(btb  + cg);

    float s_state = __ldg(s0 + (size_t)eb * Hc + cg);
    g_h[cg * Bc + eb] = __ldg(h0 + (size_t)eb * Hc + cg);

    float* b0 = s_z;
    float* b1 = s_z + ZBUF;
    float* b2 = s_z + 2 * ZBUF;

    unsigned sense0 = 0, ep = 0;
    if (tid == 0) {
        asm volatile("ld.acquire.gpu.u32 %0, [%1];"
                     : "=r"(sense0) : "l"(&g_sense) : "memory");
    }

    gbar_arrive(sense0, ep);                    // publish h0 (epoch 1)
    // prefetch x(0): X0 -> b2, X1 -> b0 (matches loop-end convention)
    stage_chunk(b2, g_xT);
    stage_chunk(b0, g_xT + (size_t)128 * Bc);

    for (int t = 0; t < Tc; t++) {
        // ============ Phase A: bb = silu(z @ Wbb + bbb), K=768 ============
        unsigned long long acc[8] = {0,0,0,0,0,0,0,0};
        // x-chunks: no dependence on h -> compute BEFORE the h-barrier wait
        cp_wait<1>(); __syncthreads();
        gemmA_chunk(b2, s_wA + ks2 * WA_SEC + 0 * 32, ks2, rgA, acc);  // X0
        cp_wait<0>(); __syncthreads();
        gemmA_chunk(b0, s_wA + ks2 * WA_SEC + 1 * 32, ks2, rgA, acc);  // X1
        gbar_wait(sense0, ep);                  // h(t) visible chip-wide
        stage_chunk(b1, g_h);                   // H0
        stage_chunk(b2, g_h + 128 * Bc);        // H1
        stage_chunk(b0, g_h + 256 * Bc);        // H2
        cp_wait<2>(); __syncthreads();
        gemmA_chunk(b1, s_wA + ks2 * WA_SEC + 2 * 32, ks2, rgA, acc);  // H0
        __syncthreads();
        stage_chunk(b1, g_h + 384 * Bc);        // H3
        cp_wait<2>(); __syncthreads();
        gemmA_chunk(b2, s_wA + ks2 * WA_SEC + 3 * 32, ks2, rgA, acc);  // H1
        cp_wait<1>(); __syncthreads();
        gemmA_chunk(b0, s_wA + ks2 * WA_SEC + 4 * 32, ks2, rgA, acc);  // H2
        cp_wait<0>(); __syncthreads();
        gemmA_chunk(b1, s_wA + ks2 * WA_SEC + 5 * 32, ks2, rgA, acc);  // H3

        // reduce 16-way ksplit (lane bits 0..3) — R8-exact
#pragma unroll
        for (int d = 1; d <= 8; d <<= 1)
#pragma unroll
            for (int q = 0; q < 8; q++) {
                unsigned long long o = __shfl_xor_sync(0xffffffffu, acc[q], d);
                add2(acc[q], acc[q], o);
            }
        if ((tid & 15) == 0) {
            float* dst = s_redA + rgA * 16;
#pragma unroll
            for (int r = 0; r < 4; r++) {
                float4 v = make_float4(lo2(acc[2*r]), hi2(acc[2*r]),
                                       lo2(acc[2*r+1]), hi2(acc[2*r+1]));
                *(float4*)(dst + r * 4) = v;
            }
        }
        __syncthreads();
        {
            float av  = s_redA[eidxA] + bbbc;
            float bbv = av / (1.0f + expf(-av));       // silu
            g_bb[cg * Bc + eb] = bbv;
        }
        gbar_arrive(sense0, ep);                        // bb barrier
        float tstv = __ldg(ts + (size_t)eb * Tc + t);   // hidden under spin
        float tn   = 1.0f / tstv;
        float wts  = (tn > 0.0f) ? expf(tn * (1.0f - 2.0f * logf(tn))) : 0.0f;
        gbar_wait(sense0, ep);

        // ====== Phase B: 4 GEMMs over bb (K=512); gate & update ======
        unsigned long long fac[8] = {0,0,0,0,0,0,0,0};
        const int t1 = (t + 1 < Tc) ? t + 1 : t;
        stage_chunk(b2, g_bb);                   // B0
        stage_chunk(b0, g_bb + 128 * Bc);        // B1
        stage_chunk(b1, g_bb + 256 * Bc);        // B2
        cp_wait<2>(); __syncthreads();
        gemmB_chunk(b2, s_wB + km * WB_SEC + 0 * 512 + mB * 4, km, rgB, fac);
        __syncthreads();
        stage_chunk(b2, g_bb + 384 * Bc);        // B3
        cp_wait<2>(); __syncthreads();
        gemmB_chunk(b0, s_wB + km * WB_SEC + 1 * 512 + mB * 4, km, rgB, fac);
        __syncthreads();
        stage_chunk(b0, g_xT + ((size_t)t1 * Dc) * Bc);         // X0(t+1)
        cp_wait<2>(); __syncthreads();
        gemmB_chunk(b1, s_wB + km * WB_SEC + 2 * 512 + mB * 4, km, rgB, fac);
        __syncthreads();
        stage_chunk(b1, g_xT + ((size_t)t1 * Dc + 128) * Bc);   // X1(t+1)
        cp_wait<2>(); __syncthreads();
        gemmB_chunk(b2, s_wB + km * WB_SEC + 3 * 512 + mB * 4, km, rgB, fac);
        // outstanding: X0(t+1), X1(t+1) — matches loop entry

        // reduce km bit0 (lane bit 4) via shfl, then padded SMEM combine
#pragma unroll
        for (int q = 0; q < 8; q++) {
            unsigned long long o = __shfl_xor_sync(0xffffffffu, fac[q], 16);
            add2(fac[q], fac[q], o);
        }
        if (lane < 16) {
            // kmHigh = warp & 1, mB = warp >> 1, rgB = lane
            float* dst = s_redB + ((warp & 1) * 4 + (warp >> 1)) * REDB_SEC
                       + lane * 20;
#pragma unroll
            for (int r = 0; r < 4; r++) {
                float4 v = make_float4(lo2(fac[2*r]), hi2(fac[2*r]),
                                       lo2(fac[2*r+1]), hi2(fac[2*r+1]));
                *(float4*)(dst + r * 4) = v;
            }
        }
        __syncthreads();
        {
            float p0 = s_redB[(0*4 + 0) * REDB_SEC + eoffB]
                     + s_redB[(1*4 + 0) * REDB_SEC + eoffB];
            float p1 = s_redB[(0*4 + 1) * REDB_SEC + eoffB]
                     + s_redB[(1*4 + 1) * REDB_SEC + eoffB];
            float p2 = s_redB[(0*4 + 2) * REDB_SEC + eoffB]
                     + s_redB[(1*4 + 2) * REDB_SEC + eoffB];
            float p3 = s_redB[(0*4 + 3) * REDB_SEC + eoffB]
                     + s_redB[(1*4 + 3) * REDB_SEC + eoffB];
            float ff1 = tanhf(p0 + bf1c);
            float ff2 = tanhf(p1 + bf2c);
            s_state += (p2 + btac) * wts + (p3 + btbc);
            float ti = 1.0f / (1.0f + expf(-s_state));
            float hn = ff1 + ti * (ff2 - ff1);
            g_h[cg * Bc + eb] = hn;
            out[((size_t)eb * Tc + t) * Hc + cg] = hn;
        }
        gbar_arrive(sense0, ep);                        // h barrier
        // rotate buffers so X0(t+1)=old b0 -> new b2, X1(t+1)=old b1 -> new b0
        float* tmp = b2; b2 = b0; b0 = b1; b1 = tmp;
    }
    cp_wait<0>();
}

// --------------------------------- launch ----------------------------------
extern "C" void kernel_launch(void* const* d_in, const int* in_sizes, int n_in,
                              void* d_out, int out_size) {
    (void)in_sizes; (void)n_in; (void)out_size;
    cudaFuncSetAttribute(cfc_persistent_kernel,
                         cudaFuncAttributeMaxDynamicSharedMemorySize, SMEM_BYTES);
    xpose_kernel<<<Tc, 256>>>((const float*)d_in[0]);
    cfc_persistent_kernel<<<NCTA, NTHR, SMEM_BYTES>>>(
        (const float*)d_in[1],
        (const float*)d_in[2],  (const float*)d_in[3],
        (const float*)d_in[4],  (const float*)d_in[5],
        (const float*)d_in[6],  (const float*)d_in[7],
        (const float*)d_in[8],  (const float*)d_in[9],
        (const float*)d_in[10], (const float*)d_in[11],
        (const float*)d_in[12], (const float*)d_in[13],
        (float*)d_out);
}